// round 7
// baseline (speedup 1.0000x reference)
#include <cuda_runtime.h>
#include <cuda_fp16.h>
#include <math.h>

#define NN 50000
#define EE 800000
#define GG 256
#define EPSF 1e-5f
#define TPB 256
#define MAXB 2048

// ---------------- scratch (rotated per layer to avoid stale-L1 within one launch) ----
__device__ __align__(256) float  g_agg0[NN * 16];
__device__ __align__(256) float  g_agg1[NN * 32];
__device__ __align__(256) float  g_agg2[NN * 64];
__device__ __align__(256) __half g_h1[NN * 32];
__device__ __align__(256) __half g_h2[NN * 64];
__device__ __align__(256) __half g_h3[NN * 128];
__device__ __align__(256) float  g_dis[NN];
__device__ __align__(256) float  g_t[NN];
__device__ __align__(256) int    g_cnt[NN];
__device__ __align__(256) int    g_rowptr[NN + 1];
__device__ __align__(256) int    g_cur[NN];
__device__ __align__(256) int    g_csr[EE];
__device__ __align__(256) int    g_bsum[MAXB];
__device__ __align__(256) float  g_stats[384];
__device__ __align__(256) float  g_pool[GG * 128];
__device__ unsigned g_barrier;

__device__ __forceinline__ float geluf(float x) {
    return 0.5f * x * (1.0f + erff(x * 0.70710678118654752f));
}
__device__ __forceinline__ void red_add_v4(float* addr, float a, float b, float c, float d) {
    asm volatile("red.global.add.v4.f32 [%0], {%1,%2,%3,%4};"
                 :: "l"(addr), "f"(a), "f"(b), "f"(c), "f"(d) : "memory");
}
__device__ __forceinline__ void acc_h(float4& s, uint2 u) {
    float2 f0 = __half22float2(*(__half2*)&u.x);
    float2 f1 = __half22float2(*(__half2*)&u.y);
    s.x += f0.x; s.y += f0.y; s.z += f1.x; s.w += f1.y;
}

// software grid barrier: monotonic counter, per-block running target
__device__ __forceinline__ void gbar(int nb, unsigned& target) {
    __syncthreads();
    if (threadIdx.x == 0) {
        __threadfence();
        atomicAdd(&g_barrier, 1u);
        target += (unsigned)nb;
        while (*(volatile unsigned*)&g_barrier < target) __nanosleep(64);
        __threadfence();
    }
    __syncthreads();
}

// ---------------- phase bodies -------------------------------------------------
// gather over fp16 messages, write fp32 activations + BN stats (layers 1-2)
template<int W>
__device__ void gather_phase(int nb, const __half* hwp, float* aggOut,
                             const float* bias, float* statsOut,
                             float* SF, int tid, int bid) {
    const int C = 4 * W;
    for (int i = tid; i < 2 * C; i += TPB) SF[i] = 0.f;
    __syncthreads();
    const uint2* __restrict__ hw = (const uint2*)hwp;
    for (int t0 = bid * TPB; t0 < NN * W; t0 += nb * TPB) {
        int t = t0 + tid;
        bool valid = t < NN * W;
        float4 r = make_float4(0.f, 0.f, 0.f, 0.f);
        if (valid) {
            int n = t / W, q = t - n * W;
            float4 s;
            { uint2 u = hw[n * W + q];
              float2 f0 = __half22float2(*(__half2*)&u.x);
              float2 f1 = __half22float2(*(__half2*)&u.y);
              s = make_float4(f0.x, f0.y, f1.x, f1.y); }
            int j = g_rowptr[n], end = g_rowptr[n + 1];
            while (j < end && (j & 3)) acc_h(s, hw[g_csr[j++] * W + q]);
            for (; j + 8 <= end; j += 8) {
                int4 a4 = *(const int4*)&g_csr[j];
                int4 b4 = *(const int4*)&g_csr[j + 4];
                uint2 u0 = hw[a4.x*W+q], u1 = hw[a4.y*W+q], u2 = hw[a4.z*W+q], u3 = hw[a4.w*W+q];
                uint2 u4 = hw[b4.x*W+q], u5 = hw[b4.y*W+q], u6 = hw[b4.z*W+q], u7 = hw[b4.w*W+q];
                acc_h(s, u0); acc_h(s, u1); acc_h(s, u2); acc_h(s, u3);
                acc_h(s, u4); acc_h(s, u5); acc_h(s, u6); acc_h(s, u7);
            }
            if (j + 4 <= end) {
                int4 a4 = *(const int4*)&g_csr[j];
                uint2 u0 = hw[a4.x*W+q], u1 = hw[a4.y*W+q], u2 = hw[a4.z*W+q], u3 = hw[a4.w*W+q];
                acc_h(s, u0); acc_h(s, u1); acc_h(s, u2); acc_h(s, u3);
                j += 4;
            }
            for (; j < end; ++j) acc_h(s, hw[g_csr[j] * W + q]);
            float d = g_dis[n];
            float4 bb = *(const float4*)&bias[q * 4];
            r.x = geluf(fmaf(d, s.x, bb.x));
            r.y = geluf(fmaf(d, s.y, bb.y));
            r.z = geluf(fmaf(d, s.z, bb.z));
            r.w = geluf(fmaf(d, s.w, bb.w));
            ((float4*)aggOut)[n * W + q] = r;
        }
        float4 r2 = make_float4(r.x * r.x, r.y * r.y, r.z * r.z, r.w * r.w);
        #pragma unroll
        for (int off = W; off < 32; off <<= 1) {
            r.x  += __shfl_down_sync(0xffffffffu, r.x,  off);
            r.y  += __shfl_down_sync(0xffffffffu, r.y,  off);
            r.z  += __shfl_down_sync(0xffffffffu, r.z,  off);
            r.w  += __shfl_down_sync(0xffffffffu, r.w,  off);
            r2.x += __shfl_down_sync(0xffffffffu, r2.x, off);
            r2.y += __shfl_down_sync(0xffffffffu, r2.y, off);
            r2.z += __shfl_down_sync(0xffffffffu, r2.z, off);
            r2.w += __shfl_down_sync(0xffffffffu, r2.w, off);
        }
        if ((tid & 31) < W) {
            int c0 = (tid % W) * 4;
            atomicAdd(&SF[c0 + 0], r.x);  atomicAdd(&SF[C + c0 + 0], r2.x);
            atomicAdd(&SF[c0 + 1], r.y);  atomicAdd(&SF[C + c0 + 1], r2.y);
            atomicAdd(&SF[c0 + 2], r.z);  atomicAdd(&SF[C + c0 + 2], r2.z);
            atomicAdd(&SF[c0 + 3], r.w);  atomicAdd(&SF[C + c0 + 3], r2.w);
        }
    }
    __syncthreads();
    for (int i = tid; i < 2 * C; i += TPB) atomicAdd(&statsOut[i], SF[i]);
}

// mm with BN fold computed once per persistent block:
// hwh[n,c] = half( ((bn(a[n,:])) @ W + b-fold)[c] * dis[n] ), bn folded as a*sc staged in smem
template<int Cin, int Cout>
__device__ void mm_phase(int nb, const float* in, const float* W,
                         const float* bn_g, const float* bn_b, const float* stats,
                         __half* hout, float* SF, int tid, int bid) {
    const int CQ = Cout / 4;
    const int NPB = TPB / CQ;   // 32,16,8 nodes per tile; NPB*Cin = 512 always
    float* sc   = SF;           // [Cin]
    float* shf  = SF + 64;      // [Cin]
    float* badd = SF + 128;     // [Cout]
    float* at   = SF + 256;     // [NPB*Cin] = 512
    if (tid < Cin) {
        float mu  = __ldcg(&stats[tid]) * (1.0f / NN);
        float var = __ldcg(&stats[Cin + tid]) * (1.0f / NN) - mu * mu;
        float s = bn_g[tid] * rsqrtf(var + EPSF);
        sc[tid]  = s;
        shf[tid] = bn_b[tid] - mu * s;
    }
    __syncthreads();
    if (tid < Cout) {
        float ba = 0.f;
        #pragma unroll 4
        for (int i = 0; i < Cin; ++i) ba = fmaf(shf[i], W[i * Cout + tid], ba);
        badd[tid] = ba;
    }
    __syncthreads();
    const float4* __restrict__ Wv = (const float4*)W;
    for (int n0 = bid * NPB; n0 < NN; n0 += nb * NPB) {
        for (int i = tid; i < NPB * Cin; i += TPB) {
            int node = n0 + i / Cin, ci = i % Cin;
            at[i] = (node < NN) ? in[node * Cin + ci] * sc[ci] : 0.f;
        }
        __syncthreads();
        int node = tid / CQ, c4 = tid - node * CQ;
        int n = n0 + node;
        if (n < NN) {
            const float* a = &at[node * Cin];
            float4 s = *(const float4*)&badd[c4 * 4];
            #pragma unroll
            for (int i = 0; i < Cin; ++i) {
                float av = a[i];
                float4 w = Wv[i * CQ + c4];
                s.x = fmaf(av, w.x, s.x); s.y = fmaf(av, w.y, s.y);
                s.z = fmaf(av, w.z, s.z); s.w = fmaf(av, w.w, s.w);
            }
            float d = g_dis[n];
            __half2 h0 = __floats2half2_rn(s.x * d, s.y * d);
            __half2 h1 = __floats2half2_rn(s.z * d, s.w * d);
            uint2 u; u.x = *(unsigned*)&h0; u.y = *(unsigned*)&h1;
            ((uint2*)hout)[n * CQ + c4] = u;
        }
        __syncthreads();
    }
}

// ---------------- the mega-kernel ------------------------------------------------
__global__ void __launch_bounds__(TPB) k_all(int nb,
    const float* x, const int* ei, const int* batch, const float* yx,
    const float* W1, const float* b1, const float* W2, const float* b2,
    const float* W3, const float* b3, const float* W4, const float* b4,
    const float* bg1, const float* bb1, const float* bg2, const float* bb2,
    const float* bg3, const float* bb3,
    const float* lw1, const float* lb1, const float* lw2, const float* lb2,
    const float* lw3, const float* lb3, const float* lw4, const float* lb4,
    float* out)
{
    __shared__ float SF[768];
    __shared__ int   SI[TPB];
    __shared__ int   SB[2];
    unsigned target = 0;
    const int tid = threadIdx.x, bid = blockIdx.x;
    const int gstride = nb * TPB;
    const int CH = (NN + nb - 1) / nb;

    // P0: zero cnt / stats / pool
    for (int i = bid * TPB + tid; i < NN; i += gstride)      g_cnt[i] = 0;
    for (int i = bid * TPB + tid; i < 384; i += gstride)     g_stats[i] = 0.f;
    for (int i = bid * TPB + tid; i < GG * 128; i += gstride) g_pool[i] = 0.f;
    gbar(nb, target);

    // P1: in-degree histogram
    for (int e = bid * TPB + tid; e < EE; e += gstride)
        atomicAdd(&g_cnt[ei[EE + e]], 1);
    gbar(nb, target);

    // P2: per-block chunk sums
    {
        int lo = bid * CH, hi = min(lo + CH, NN);
        int s = 0;
        for (int i = lo + tid; i < hi; i += TPB) s += __ldcg(&g_cnt[i]);
        SI[tid] = s;
        __syncthreads();
        for (int o = TPB / 2; o > 0; o >>= 1) {
            if (tid < o) SI[tid] += SI[tid + o];
            __syncthreads();
        }
        if (tid == 0) g_bsum[bid] = SI[0];
    }
    gbar(nb, target);

    // P3: block 0 scans the nb block sums (exclusive)
    if (bid == 0) {
        int per = (nb + TPB - 1) / TPB;   // <= 8
        int loc[8]; int s = 0;
        for (int k = 0; k < per; ++k) {
            int idx = tid * per + k;
            int v = (idx < nb) ? __ldcg(&g_bsum[idx]) : 0;
            loc[k] = v; s += v;
        }
        SI[tid] = s;
        __syncthreads();
        for (int o = 1; o < TPB; o <<= 1) {
            int u = (tid >= o) ? SI[tid - o] : 0;
            __syncthreads();
            SI[tid] += u;
            __syncthreads();
        }
        int run = SI[tid] - s;
        for (int k = 0; k < per; ++k) {
            int idx = tid * per + k;
            if (idx < nb) { g_bsum[idx] = run; run += loc[k]; }
        }
        if (tid == 0) g_rowptr[NN] = EE;
    }
    gbar(nb, target);

    // P4: rowptr / cursors / dis / t
    {
        int lo = bid * CH, hi = min(lo + CH, NN);
        int run = (lo < NN) ? __ldcg(&g_bsum[bid]) : 0;
        for (int base = lo; base < hi; base += TPB) {
            int i = base + tid;
            int c = (i < hi) ? __ldcg(&g_cnt[i]) : 0;
            SI[tid] = c;
            __syncthreads();
            for (int o = 1; o < TPB; o <<= 1) {
                int u = (tid >= o) ? SI[tid - o] : 0;
                __syncthreads();
                SI[tid] += u;
                __syncthreads();
            }
            int incl = SI[tid];
            int tot  = SI[TPB - 1];
            if (i < hi) {
                int rp = run + incl - c;
                g_rowptr[i] = rp;
                g_cur[i]    = rp;
                float d = rsqrtf((float)c + 1.0f);
                g_dis[i] = d;
                g_t[i]   = x[i] * d;
            }
            run += tot;
            __syncthreads();
        }
    }
    gbar(nb, target);

    // P5: fill CSR
    for (int e = bid * TPB + tid; e < EE; e += gstride) {
        int pos = atomicAdd(&g_cur[ei[EE + e]], 1);
        g_csr[pos] = ei[e];
    }
    gbar(nb, target);

    // P6: layer 0 (rank-1) gather + expand + gelu + stats
    for (int n0 = bid * TPB; n0 < NN; n0 += gstride) {
        int n = n0 + tid;
        bool valid = n < NN;
        float u = 0.f;
        if (valid) {
            int j = g_rowptr[n], end = g_rowptr[n + 1];
            float s = g_t[n];
            float s0 = 0.f, s1 = 0.f, s2 = 0.f, s3 = 0.f;
            while (j < end && (j & 3)) s0 += g_t[g_csr[j++]];
            for (; j + 4 <= end; j += 4) {
                int4 i4 = *(const int4*)&g_csr[j];
                s0 += g_t[i4.x]; s1 += g_t[i4.y];
                s2 += g_t[i4.z]; s3 += g_t[i4.w];
            }
            for (; j < end; ++j) s0 += g_t[g_csr[j]];
            u = g_dis[n] * (s + (s0 + s1) + (s2 + s3));
        }
        float sm[16], sq[16], vv[16];
        #pragma unroll
        for (int c = 0; c < 16; ++c) {
            float v = valid ? geluf(fmaf(__ldg(&W1[c]), u, __ldg(&b1[c]))) : 0.f;
            vv[c] = v; sm[c] = v; sq[c] = v * v;
        }
        if (valid) {
            float4* o4 = (float4*)&g_agg0[n * 16];
            o4[0] = make_float4(vv[0], vv[1], vv[2], vv[3]);
            o4[1] = make_float4(vv[4], vv[5], vv[6], vv[7]);
            o4[2] = make_float4(vv[8], vv[9], vv[10], vv[11]);
            o4[3] = make_float4(vv[12], vv[13], vv[14], vv[15]);
        }
        #pragma unroll
        for (int off = 16; off > 0; off >>= 1) {
            #pragma unroll
            for (int c = 0; c < 16; ++c) {
                sm[c] += __shfl_xor_sync(0xffffffffu, sm[c], off);
                sq[c] += __shfl_xor_sync(0xffffffffu, sq[c], off);
            }
        }
        if ((tid & 31) == 0) {
            #pragma unroll
            for (int c = 0; c < 16; ++c) {
                atomicAdd(&g_stats[c], sm[c]);
                atomicAdd(&g_stats[16 + c], sq[c]);
            }
        }
    }
    gbar(nb, target);

    // P7-P8: layer 1 (16->32)
    mm_phase<16, 32>(nb, g_agg0, W2, bg1, bb1, g_stats + 0,   g_h1, SF, tid, bid);
    gbar(nb, target);
    gather_phase<8>(nb, g_h1, g_agg1, b2, g_stats + 128, SF, tid, bid);
    gbar(nb, target);

    // P9-P10: layer 2 (32->64)
    mm_phase<32, 64>(nb, g_agg1, W3, bg2, bb2, g_stats + 128, g_h2, SF, tid, bid);
    gbar(nb, target);
    gather_phase<16>(nb, g_h2, g_agg2, b3, g_stats + 256, SF, tid, bid);
    gbar(nb, target);

    // P11: layer 3 mm (64->128)
    mm_phase<64, 128>(nb, g_agg2, W4, bg3, bb3, g_stats + 256, g_h3, SF, tid, bid);
    gbar(nb, target);

    // P12: layer 3 gather + gelu + mean-pool sum
    {
        const int W = 32;
        const uint2* __restrict__ hw = (const uint2*)g_h3;
        for (int t = bid * TPB + tid; t < NN * W; t += gstride) {
            int n = t / W, q = t - n * W;
            float4 s;
            { uint2 u = hw[n * W + q];
              float2 f0 = __half22float2(*(__half2*)&u.x);
              float2 f1 = __half22float2(*(__half2*)&u.y);
              s = make_float4(f0.x, f0.y, f1.x, f1.y); }
            int j = g_rowptr[n], end = g_rowptr[n + 1];
            while (j < end && (j & 3)) acc_h(s, hw[g_csr[j++] * W + q]);
            for (; j + 8 <= end; j += 8) {
                int4 a4 = *(const int4*)&g_csr[j];
                int4 b4 = *(const int4*)&g_csr[j + 4];
                uint2 u0 = hw[a4.x*W+q], u1 = hw[a4.y*W+q], u2 = hw[a4.z*W+q], u3 = hw[a4.w*W+q];
                uint2 u4 = hw[b4.x*W+q], u5 = hw[b4.y*W+q], u6 = hw[b4.z*W+q], u7 = hw[b4.w*W+q];
                acc_h(s, u0); acc_h(s, u1); acc_h(s, u2); acc_h(s, u3);
                acc_h(s, u4); acc_h(s, u5); acc_h(s, u6); acc_h(s, u7);
            }
            if (j + 4 <= end) {
                int4 a4 = *(const int4*)&g_csr[j];
                uint2 u0 = hw[a4.x*W+q], u1 = hw[a4.y*W+q], u2 = hw[a4.z*W+q], u3 = hw[a4.w*W+q];
                acc_h(s, u0); acc_h(s, u1); acc_h(s, u2); acc_h(s, u3);
                j += 4;
            }
            for (; j < end; ++j) acc_h(s, hw[g_csr[j] * W + q]);
            float d = g_dis[n];
            float4 bb = *(const float4*)&b4[q * 4];
            int g = batch[n];
            red_add_v4(&g_pool[g * 128 + q * 4],
                       geluf(fmaf(d, s.x, bb.x)), geluf(fmaf(d, s.y, bb.y)),
                       geluf(fmaf(d, s.z, bb.z)), geluf(fmaf(d, s.w, bb.w)));
        }
    }
    gbar(nb, target);

    // P13: fused MLP head, one graph per block (looped)
    {
        float* z  = SF;         // [136]
        float* a1 = SF + 144;   // [128]
        float* a2 = SF + 288;   // [64]
        float* a3 = SF + 384;   // [32]
        for (int g = bid; g < GG; g += nb) {
            if (tid < 2) {
                int key = g + tid;
                int lo = 0, hi = NN;
                while (lo < hi) {
                    int mid = (lo + hi) >> 1;
                    if (batch[mid] < key) lo = mid + 1; else hi = mid;
                }
                SB[tid] = lo;
            }
            __syncthreads();
            float inv = 1.0f / fmaxf((float)(SB[1] - SB[0]), 1.0f);
            for (int j = tid; j < 135; j += TPB)
                z[j] = (j < 128) ? g_pool[g * 128 + j] * inv : yx[g * 7 + (j - 128)];
            __syncthreads();
            if (tid < 128) {
                float s = lb1[tid];
                #pragma unroll 5
                for (int i = 0; i < 135; ++i) s = fmaf(z[i], lw1[i * 128 + tid], s);
                a1[tid] = geluf(s);
            }
            __syncthreads();
            if (tid < 64) {
                float s = lb2[tid];
                #pragma unroll 8
                for (int i = 0; i < 128; ++i) s = fmaf(a1[i], lw2[i * 64 + tid], s);
                a2[tid] = geluf(s);
            }
            __syncthreads();
            if (tid < 32) {
                float s = lb3[tid];
                #pragma unroll 8
                for (int i = 0; i < 64; ++i) s = fmaf(a2[i], lw3[i * 32 + tid], s);
                a3[tid] = geluf(s);
            }
            __syncthreads();
            if (tid < 2) {
                float s = lb4[tid];
                #pragma unroll
                for (int i = 0; i < 32; ++i) s = fmaf(a3[i], lw4[i * 2 + tid], s);
                out[g * 2 + tid] = 1.0f / (1.0f + expf(-s));
            }
            __syncthreads();
        }
    }
}

// ---------------- host -------------------------------------------------------------
extern "C" void kernel_launch(void* const* d_in, const int* in_sizes, int n_in,
                              void* d_out, int out_size) {
    const float* x     = (const float*)d_in[0];
    const int*   ei    = (const int*)d_in[1];
    const int*   batch = (const int*)d_in[2];
    const float* yx    = (const float*)d_in[3];

    void* p_bar;
    cudaGetSymbolAddress(&p_bar, g_barrier);

    int dev = 0;
    cudaGetDevice(&dev);
    int nsm = 0, occ = 0;
    cudaDeviceGetAttribute(&nsm, cudaDevAttrMultiProcessorCount, dev);
    cudaOccupancyMaxActiveBlocksPerMultiprocessor(&occ, k_all, TPB, 0);
    if (occ < 1) occ = 1;
    int nb = nsm * occ;
    if (nb > MAXB) nb = MAXB;

    cudaMemsetAsync(p_bar, 0, sizeof(unsigned));
    k_all<<<nb, TPB>>>(nb,
        x, ei, batch, yx,
        (const float*)d_in[4],  (const float*)d_in[5],
        (const float*)d_in[6],  (const float*)d_in[7],
        (const float*)d_in[8],  (const float*)d_in[9],
        (const float*)d_in[10], (const float*)d_in[11],
        (const float*)d_in[12], (const float*)d_in[13],
        (const float*)d_in[14], (const float*)d_in[15],
        (const float*)d_in[16], (const float*)d_in[17],
        (const float*)d_in[18], (const float*)d_in[19],
        (const float*)d_in[20], (const float*)d_in[21],
        (const float*)d_in[22], (const float*)d_in[23],
        (const float*)d_in[24], (const float*)d_in[25],
        (float*)d_out);
}

// round 8
// speedup vs baseline: 1.1881x; 1.1881x over previous
#include <cuda_runtime.h>
#include <cuda_fp16.h>
#include <math.h>

#define NN 50000
#define EE 800000
#define GG 256
#define EPSF 1e-5f
#define SCAN_B 196   // ceil(50000/256)

// ---------------- scratch ----------------------------------------------------
__device__ __align__(256) __half g_y[NN * 64];      // y_l * dis, fp16 (max 64 ch)
__device__ __align__(256) float  g_Q[NN * 64];      // aggregated input, fp32
__device__ __align__(256) float  g_dis[NN];
__device__ __align__(256) float  g_rs[NN];          // dis*(dis + sum dis[src])
__device__ __align__(256) float2 g_td[NN];          // (x*dis, dis)
__device__ __align__(256) int    g_cnt[NN];
__device__ __align__(256) int    g_rowptr[NN + 1];
__device__ __align__(256) int    g_cur[NN];
__device__ __align__(256) int    g_csr[EE];
__device__ __align__(256) int    g_bsum[SCAN_B];
__device__ __align__(256) float  g_stats[384];
__device__ __align__(256) float  g_pool[GG * 128];

__device__ __forceinline__ float geluf(float x) {
    return 0.5f * x * (1.0f + erff(x * 0.70710678118654752f));
}
__device__ __forceinline__ void red_add_v4(float* addr, float a, float b, float c, float d) {
    asm volatile("red.global.add.v4.f32 [%0], {%1,%2,%3,%4};"
                 :: "l"(addr), "f"(a), "f"(b), "f"(c), "f"(d) : "memory");
}
__device__ __forceinline__ void acc_h(float4& s, uint2 u) {
    float2 f0 = __half22float2(*(__half2*)&u.x);
    float2 f1 = __half22float2(*(__half2*)&u.y);
    s.x += f0.x; s.y += f0.y; s.z += f1.x; s.w += f1.y;
}

// ---------------- CSR build ---------------------------------------------------
__global__ void k_hist(const int* __restrict__ ei) {
    int e = blockIdx.x * blockDim.x + threadIdx.x;
    if (e < EE) atomicAdd(&g_cnt[ei[EE + e]], 1);
}
__global__ void k_scanA() {
    __shared__ int sh[256];
    int i = blockIdx.x * 256 + threadIdx.x;
    sh[threadIdx.x] = (i < NN) ? g_cnt[i] : 0;
    __syncthreads();
    for (int o = 128; o > 0; o >>= 1) {
        if (threadIdx.x < o) sh[threadIdx.x] += sh[threadIdx.x + o];
        __syncthreads();
    }
    if (threadIdx.x == 0) g_bsum[blockIdx.x] = sh[0];
}
__global__ void k_scanB() {
    __shared__ int sh[256];
    int t = threadIdx.x;
    int v = (t < SCAN_B) ? g_bsum[t] : 0;
    sh[t] = v;
    __syncthreads();
    for (int o = 1; o < 256; o <<= 1) {
        int u = (t >= o) ? sh[t - o] : 0;
        __syncthreads();
        sh[t] += u;
        __syncthreads();
    }
    if (t < SCAN_B) g_bsum[t] = sh[t] - v;
    if (t == 0) g_rowptr[NN] = EE;
}
__global__ void k_scanC(const float* __restrict__ x) {
    __shared__ int sh[256];
    int i = blockIdx.x * 256 + threadIdx.x;
    int t = threadIdx.x;
    int c = (i < NN) ? g_cnt[i] : 0;
    sh[t] = c;
    __syncthreads();
    for (int o = 1; o < 256; o <<= 1) {
        int u = (t >= o) ? sh[t - o] : 0;
        __syncthreads();
        sh[t] += u;
        __syncthreads();
    }
    if (i < NN) {
        int rp = g_bsum[blockIdx.x] + sh[t] - c;
        g_rowptr[i] = rp;
        g_cur[i]    = rp;
        float d = rsqrtf((float)c + 1.0f);
        g_dis[i]  = d;
        g_td[i]   = make_float2(x[i] * d, d);
    }
}
__global__ void k_fill(const int* __restrict__ ei) {
    int e = blockIdx.x * blockDim.x + threadIdx.x;
    if (e < EE) {
        int pos = atomicAdd(&g_cur[ei[EE + e]], 1);
        g_csr[pos] = ei[e];
    }
}

// ---------------- layer 0: scalar gather (x*dis AND dis) + expand + gelu + stats
__global__ void k_l0(const float* __restrict__ W1, const float* __restrict__ b1,
                     float* __restrict__ statsOut) {
    int n = blockIdx.x * 256 + threadIdx.x;
    bool valid = n < NN;
    float u = 0.f, d = 0.f;
    if (valid) {
        float2 self = g_td[n];
        d = self.y;
        float st = self.x, sd = self.y;
        int j = g_rowptr[n], end = g_rowptr[n + 1];
        while (j < end && (j & 3)) { float2 a = g_td[g_csr[j++]]; st += a.x; sd += a.y; }
        for (; j + 4 <= end; j += 4) {
            int4 i4 = *(const int4*)&g_csr[j];
            float2 a0 = g_td[i4.x], a1 = g_td[i4.y], a2 = g_td[i4.z], a3 = g_td[i4.w];
            st += (a0.x + a1.x) + (a2.x + a3.x);
            sd += (a0.y + a1.y) + (a2.y + a3.y);
        }
        for (; j < end; ++j) { float2 a = g_td[g_csr[j]]; st += a.x; sd += a.y; }
        u = d * st;
        g_rs[n] = d * sd;
    }
    float sm[16], sq[16], vv[16];
    #pragma unroll
    for (int c = 0; c < 16; ++c) {
        float v = valid ? geluf(fmaf(__ldg(&W1[c]), u, __ldg(&b1[c]))) : 0.f;
        vv[c] = v; sm[c] = v; sq[c] = v * v;
    }
    if (valid) {
        // write y0*dis as fp16 (16 halves = 2x uint4)
        uint4 o0, o1;
        __half2 h;
        h = __floats2half2_rn(vv[0]*d,  vv[1]*d);  o0.x = *(unsigned*)&h;
        h = __floats2half2_rn(vv[2]*d,  vv[3]*d);  o0.y = *(unsigned*)&h;
        h = __floats2half2_rn(vv[4]*d,  vv[5]*d);  o0.z = *(unsigned*)&h;
        h = __floats2half2_rn(vv[6]*d,  vv[7]*d);  o0.w = *(unsigned*)&h;
        h = __floats2half2_rn(vv[8]*d,  vv[9]*d);  o1.x = *(unsigned*)&h;
        h = __floats2half2_rn(vv[10]*d, vv[11]*d); o1.y = *(unsigned*)&h;
        h = __floats2half2_rn(vv[12]*d, vv[13]*d); o1.z = *(unsigned*)&h;
        h = __floats2half2_rn(vv[14]*d, vv[15]*d); o1.w = *(unsigned*)&h;
        ((uint4*)&g_y[n * 16])[0] = o0;
        ((uint4*)&g_y[n * 16])[1] = o1;
    }
    #pragma unroll
    for (int off = 16; off > 0; off >>= 1) {
        #pragma unroll
        for (int c = 0; c < 16; ++c) {
            sm[c] += __shfl_xor_sync(0xffffffffu, sm[c], off);
            sq[c] += __shfl_xor_sync(0xffffffffu, sq[c], off);
        }
    }
    if ((threadIdx.x & 31) == 0) {
        #pragma unroll
        for (int c = 0; c < 16; ++c) {
            atomicAdd(&statsOut[c], sm[c]);
            atomicAdd(&statsOut[16 + c], sq[c]);
        }
    }
}

// ---------------- gather of y_h (Cin channels, fp16) -> Q fp32 -----------------
template<int WQ>   // WQ = Cin/4 quads
__global__ void k_gatherQ() {
    int t = blockIdx.x * blockDim.x + threadIdx.x;
    if (t >= NN * WQ) return;
    int n = t / WQ, q = t - n * WQ;
    const uint2* __restrict__ hw = (const uint2*)g_y;
    float4 s;
    { uint2 u = hw[n * WQ + q];
      float2 f0 = __half22float2(*(__half2*)&u.x);
      float2 f1 = __half22float2(*(__half2*)&u.y);
      s = make_float4(f0.x, f0.y, f1.x, f1.y); }
    int j = g_rowptr[n], end = g_rowptr[n + 1];
    while (j < end && (j & 3)) acc_h(s, hw[g_csr[j++] * WQ + q]);
    for (; j + 8 <= end; j += 8) {
        int4 a4 = *(const int4*)&g_csr[j];
        int4 b4 = *(const int4*)&g_csr[j + 4];
        uint2 u0 = hw[a4.x*WQ+q], u1 = hw[a4.y*WQ+q], u2 = hw[a4.z*WQ+q], u3 = hw[a4.w*WQ+q];
        uint2 u4 = hw[b4.x*WQ+q], u5 = hw[b4.y*WQ+q], u6 = hw[b4.z*WQ+q], u7 = hw[b4.w*WQ+q];
        acc_h(s, u0); acc_h(s, u1); acc_h(s, u2); acc_h(s, u3);
        acc_h(s, u4); acc_h(s, u5); acc_h(s, u6); acc_h(s, u7);
    }
    if (j + 4 <= end) {
        int4 a4 = *(const int4*)&g_csr[j];
        uint2 u0 = hw[a4.x*WQ+q], u1 = hw[a4.y*WQ+q], u2 = hw[a4.z*WQ+q], u3 = hw[a4.w*WQ+q];
        acc_h(s, u0); acc_h(s, u1); acc_h(s, u2); acc_h(s, u3);
        j += 4;
    }
    for (; j < end; ++j) acc_h(s, hw[g_csr[j] * WQ + q]);
    float d = g_dis[n];
    ((float4*)g_Q)[n * WQ + q] = make_float4(s.x * d, s.y * d, s.z * d, s.w * d);
}

// ---------------- mm: u = sc*Q + shf*rs; y = gelu(u@W + b); stats or pool ------
template<int Cin, int Cout, bool POOL>
__global__ void k_mm(const float* __restrict__ W, const float* __restrict__ bias,
                     const float* __restrict__ gam, const float* __restrict__ bet,
                     const float* __restrict__ statsIn, float* __restrict__ statsOut,
                     const int* __restrict__ batch) {
    const int CQ = Cout / 4;
    const int NPB = 256 / CQ;
    __shared__ float sc[64], shf[64], ut[512];   // NPB*Cin == 512 for all layers
    __shared__ float sh[256];                    // 2*Cout <= 256
    int tid = threadIdx.x;
    if (tid < Cin) {
        float mu  = statsIn[tid] * (1.0f / NN);
        float var = statsIn[Cin + tid] * (1.0f / NN) - mu * mu;
        float s = gam[tid] * rsqrtf(var + EPSF);
        sc[tid]  = s;
        shf[tid] = bet[tid] - mu * s;
    }
    if (!POOL) {
        for (int i = tid; i < 2 * Cout; i += 256) sh[i] = 0.f;
    }
    __syncthreads();

    int n0 = blockIdx.x * NPB;
    for (int i = tid; i < NPB * Cin; i += 256) {
        int node = n0 + i / Cin, ci = i % Cin;
        ut[i] = (node < NN) ? fmaf(shf[ci], g_rs[node], sc[ci] * g_Q[node * Cin + ci]) : 0.f;
    }
    __syncthreads();

    int node = tid / CQ, c4 = tid - node * CQ;
    int n = n0 + node;
    bool valid = n < NN;
    const float4* __restrict__ Wv = (const float4*)W;
    float4 r = make_float4(0.f, 0.f, 0.f, 0.f);
    if (valid) {
        const float* a = &ut[node * Cin];
        float4 s = *(const float4*)&bias[c4 * 4];
        #pragma unroll
        for (int i = 0; i < Cin; ++i) {
            float av = a[i];
            float4 w = Wv[i * CQ + c4];
            s.x = fmaf(av, w.x, s.x); s.y = fmaf(av, w.y, s.y);
            s.z = fmaf(av, w.z, s.z); s.w = fmaf(av, w.w, s.w);
        }
        r.x = geluf(s.x); r.y = geluf(s.y); r.z = geluf(s.z); r.w = geluf(s.w);
        if (POOL) {
            int g = batch[n];
            red_add_v4(&g_pool[g * 128 + c4 * 4], r.x, r.y, r.z, r.w);
        } else {
            float d = g_dis[n];
            __half2 h0 = __floats2half2_rn(r.x * d, r.y * d);
            __half2 h1 = __floats2half2_rn(r.z * d, r.w * d);
            uint2 u; u.x = *(unsigned*)&h0; u.y = *(unsigned*)&h1;
            ((uint2*)g_y)[n * CQ + c4] = u;
        }
    }
    if (!POOL) {
        float4 r2 = make_float4(r.x * r.x, r.y * r.y, r.z * r.z, r.w * r.w);
        #pragma unroll
        for (int off = CQ; off < 32; off <<= 1) {
            r.x  += __shfl_down_sync(0xffffffffu, r.x,  off);
            r.y  += __shfl_down_sync(0xffffffffu, r.y,  off);
            r.z  += __shfl_down_sync(0xffffffffu, r.z,  off);
            r.w  += __shfl_down_sync(0xffffffffu, r.w,  off);
            r2.x += __shfl_down_sync(0xffffffffu, r2.x, off);
            r2.y += __shfl_down_sync(0xffffffffu, r2.y, off);
            r2.z += __shfl_down_sync(0xffffffffu, r2.z, off);
            r2.w += __shfl_down_sync(0xffffffffu, r2.w, off);
        }
        if ((tid & 31) < CQ) {
            int c0 = (tid % CQ) * 4;
            atomicAdd(&sh[c0 + 0], r.x);  atomicAdd(&sh[Cout + c0 + 0], r2.x);
            atomicAdd(&sh[c0 + 1], r.y);  atomicAdd(&sh[Cout + c0 + 1], r2.y);
            atomicAdd(&sh[c0 + 2], r.z);  atomicAdd(&sh[Cout + c0 + 2], r2.z);
            atomicAdd(&sh[c0 + 3], r.w);  atomicAdd(&sh[Cout + c0 + 3], r2.w);
        }
        __syncthreads();
        for (int i = tid; i < 2 * Cout; i += 256) atomicAdd(&statsOut[i], sh[i]);
    }
}

// ---------------- fused MLP head -------------------------------------------------
__global__ void k_head(const int* __restrict__ batch, const float* __restrict__ yx,
                       const float* __restrict__ lw1, const float* __restrict__ lb1,
                       const float* __restrict__ lw2, const float* __restrict__ lb2,
                       const float* __restrict__ lw3, const float* __restrict__ lb3,
                       const float* __restrict__ lw4, const float* __restrict__ lb4,
                       float* __restrict__ out) {
    int g = blockIdx.x, tid = threadIdx.x;
    __shared__ float z[136], a1[128], a2[64], a3[32];
    __shared__ int bounds[2];
    if (tid < 2) {
        int key = g + tid;
        int lo = 0, hi = NN;
        while (lo < hi) {
            int mid = (lo + hi) >> 1;
            if (batch[mid] < key) lo = mid + 1; else hi = mid;
        }
        bounds[tid] = lo;
    }
    __syncthreads();
    float inv = 1.0f / fmaxf((float)(bounds[1] - bounds[0]), 1.0f);
    for (int j = tid; j < 135; j += 128)
        z[j] = (j < 128) ? g_pool[g * 128 + j] * inv : yx[g * 7 + (j - 128)];
    __syncthreads();
    {
        float s = lb1[tid];
        #pragma unroll 5
        for (int i = 0; i < 135; ++i) s = fmaf(z[i], lw1[i * 128 + tid], s);
        a1[tid] = geluf(s);
    }
    __syncthreads();
    if (tid < 64) {
        float s = lb2[tid];
        #pragma unroll 8
        for (int i = 0; i < 128; ++i) s = fmaf(a1[i], lw2[i * 64 + tid], s);
        a2[tid] = geluf(s);
    }
    __syncthreads();
    if (tid < 32) {
        float s = lb3[tid];
        #pragma unroll 8
        for (int i = 0; i < 64; ++i) s = fmaf(a2[i], lw3[i * 32 + tid], s);
        a3[tid] = geluf(s);
    }
    __syncthreads();
    if (tid < 2) {
        float s = lb4[tid];
        #pragma unroll
        for (int i = 0; i < 32; ++i) s = fmaf(a3[i], lw4[i * 2 + tid], s);
        out[g * 2 + tid] = 1.0f / (1.0f + expf(-s));
    }
}

// ---------------- host -------------------------------------------------------------
static inline int gs(int n) { return (n + 255) / 256; }

extern "C" void kernel_launch(void* const* d_in, const int* in_sizes, int n_in,
                              void* d_out, int out_size) {
    const float* x     = (const float*)d_in[0];
    const int*   ei    = (const int*)d_in[1];
    const int*   batch = (const int*)d_in[2];
    const float* yx    = (const float*)d_in[3];
    const float* W[4]  = {(const float*)d_in[4], (const float*)d_in[6],
                          (const float*)d_in[8], (const float*)d_in[10]};
    const float* B[4]  = {(const float*)d_in[5], (const float*)d_in[7],
                          (const float*)d_in[9], (const float*)d_in[11]};
    const float* Gm[3] = {(const float*)d_in[12], (const float*)d_in[14], (const float*)d_in[16]};
    const float* Be[3] = {(const float*)d_in[13], (const float*)d_in[15], (const float*)d_in[17]};
    const float* LW[4] = {(const float*)d_in[18], (const float*)d_in[20],
                          (const float*)d_in[22], (const float*)d_in[24]};
    const float* LB[4] = {(const float*)d_in[19], (const float*)d_in[21],
                          (const float*)d_in[23], (const float*)d_in[25]};

    void *p_cnt, *p_pool, *p_stats;
    cudaGetSymbolAddress(&p_cnt,   g_cnt);
    cudaGetSymbolAddress(&p_pool,  g_pool);
    cudaGetSymbolAddress(&p_stats, g_stats);
    float* stats = (float*)p_stats;

    cudaMemsetAsync(p_cnt,   0, NN * sizeof(int));
    cudaMemsetAsync(p_pool,  0, GG * 128 * sizeof(float));
    cudaMemsetAsync(p_stats, 0, 384 * sizeof(float));

    k_hist <<<gs(EE), 256>>>(ei);
    k_scanA<<<SCAN_B, 256>>>();
    k_scanB<<<1, 256>>>();
    k_scanC<<<SCAN_B, 256>>>(x);
    k_fill <<<gs(EE), 256>>>(ei);

    // layer 0: scalar gather (x*dis, dis) -> y0h fp16[16] + rs + stats0
    k_l0<<<gs(NN), 256>>>(W[0], B[0], stats + 0);

    // layer 1: gather y0h (16ch) -> Q; mm 16->32 (+bn0 fold, gelu, stats1)
    k_gatherQ<4> <<<gs(NN * 4), 256>>>();
    k_mm<16, 32, false><<<(NN + 31) / 32, 256>>>(W[1], B[1], Gm[0], Be[0],
                                                 stats + 0, stats + 128, batch);

    // layer 2: gather y1h (32ch) -> Q; mm 32->64 (+bn1 fold, gelu, stats2)
    k_gatherQ<8> <<<gs(NN * 8), 256>>>();
    k_mm<32, 64, false><<<(NN + 15) / 16, 256>>>(W[2], B[2], Gm[1], Be[1],
                                                 stats + 128, stats + 256, batch);

    // layer 3: gather y2h (64ch) -> Q; mm 64->128 (+bn2 fold, gelu, pool)
    k_gatherQ<16><<<gs(NN * 16), 256>>>();
    k_mm<64, 128, true><<<(NN + 7) / 8, 256>>>(W[3], B[3], Gm[2], Be[2],
                                               stats + 256, nullptr, batch);

    k_head<<<GG, 128>>>(batch, yx, LW[0], LB[0], LW[1], LB[1],
                        LW[2], LB[2], LW[3], LB[3], (float*)d_out);
}

// round 10
// speedup vs baseline: 1.2220x; 1.0286x over previous
#include <cuda_runtime.h>
#include <cuda_fp16.h>
#include <math.h>

#define NN 50000
#define EE 800000
#define GG 256
#define EPSF 1e-5f
#define SCAN_B 196   // ceil(50000/256)

// ---------------- scratch ----------------------------------------------------
__device__ __align__(256) __half g_ya[NN * 64];     // message ping buffer
__device__ __align__(256) __half g_yb[NN * 64];     // message pong buffer
__device__ __align__(256) float  g_dis[NN];
__device__ __align__(256) float  g_rs[NN];          // dis*(dis + sum dis[src])
__device__ __align__(256) float2 g_td[NN];          // (x*dis, dis)
__device__ __align__(256) int    g_cnt[NN];
__device__ __align__(256) int    g_rowptr[NN + 1];
__device__ __align__(256) int    g_cur[NN];
__device__ __align__(256) int    g_csr[EE];
__device__ __align__(256) int    g_bsum[SCAN_B];
__device__ __align__(256) float  g_stats[384];
__device__ __align__(256) float  g_pool[GG * 128];

__device__ __forceinline__ float geluf(float x) {
    return 0.5f * x * (1.0f + erff(x * 0.70710678118654752f));
}
__device__ __forceinline__ void red_add_v4(float* addr, float a, float b, float c, float d) {
    asm volatile("red.global.add.v4.f32 [%0], {%1,%2,%3,%4};"
                 :: "l"(addr), "f"(a), "f"(b), "f"(c), "f"(d) : "memory");
}
__device__ __forceinline__ void acc_h(float4& s, uint2 u) {
    float2 f0 = __half22float2(*(__half2*)&u.x);
    float2 f1 = __half22float2(*(__half2*)&u.y);
    s.x += f0.x; s.y += f0.y; s.z += f1.x; s.w += f1.y;
}

// ---------------- CSR build ---------------------------------------------------
__global__ void k_hist(const int* __restrict__ ei) {
    int e = blockIdx.x * blockDim.x + threadIdx.x;
    if (e < EE) atomicAdd(&g_cnt[ei[EE + e]], 1);
}
__global__ void k_scanA() {
    __shared__ int sh[256];
    int i = blockIdx.x * 256 + threadIdx.x;
    sh[threadIdx.x] = (i < NN) ? g_cnt[i] : 0;
    __syncthreads();
    for (int o = 128; o > 0; o >>= 1) {
        if (threadIdx.x < o) sh[threadIdx.x] += sh[threadIdx.x + o];
        __syncthreads();
    }
    if (threadIdx.x == 0) g_bsum[blockIdx.x] = sh[0];
}
__global__ void k_scanB() {
    __shared__ int sh[256];
    int t = threadIdx.x;
    int v = (t < SCAN_B) ? g_bsum[t] : 0;
    sh[t] = v;
    __syncthreads();
    for (int o = 1; o < 256; o <<= 1) {
        int u = (t >= o) ? sh[t - o] : 0;
        __syncthreads();
        sh[t] += u;
        __syncthreads();
    }
    if (t < SCAN_B) g_bsum[t] = sh[t] - v;
    if (t == 0) g_rowptr[NN] = EE;
}
__global__ void k_scanC(const float* __restrict__ x) {
    __shared__ int sh[256];
    int i = blockIdx.x * 256 + threadIdx.x;
    int t = threadIdx.x;
    int c = (i < NN) ? g_cnt[i] : 0;
    sh[t] = c;
    __syncthreads();
    for (int o = 1; o < 256; o <<= 1) {
        int u = (t >= o) ? sh[t - o] : 0;
        __syncthreads();
        sh[t] += u;
        __syncthreads();
    }
    if (i < NN) {
        int rp = g_bsum[blockIdx.x] + sh[t] - c;
        g_rowptr[i] = rp;
        g_cur[i]    = rp;
        float d = rsqrtf((float)c + 1.0f);
        g_dis[i]  = d;
        g_td[i]   = make_float2(x[i] * d, d);
    }
}
__global__ void k_fill(const int* __restrict__ ei) {
    int e = blockIdx.x * blockDim.x + threadIdx.x;
    if (e < EE) {
        int pos = atomicAdd(&g_cur[ei[EE + e]], 1);
        g_csr[pos] = ei[e];
    }
}

// ---------------- layer 0: scalar gather (x*dis AND dis) + expand + gelu + stats
__global__ void k_l0(const float* __restrict__ W1, const float* __restrict__ b1,
                     float* __restrict__ statsOut) {
    int n = blockIdx.x * 256 + threadIdx.x;
    bool valid = n < NN;
    float u = 0.f, d = 0.f;
    if (valid) {
        float2 self = g_td[n];
        d = self.y;
        float st = self.x, sd = self.y;
        int j = g_rowptr[n], end = g_rowptr[n + 1];
        while (j < end && (j & 3)) { float2 a = g_td[g_csr[j++]]; st += a.x; sd += a.y; }
        for (; j + 4 <= end; j += 4) {
            int4 i4 = *(const int4*)&g_csr[j];
            float2 a0 = g_td[i4.x], a1 = g_td[i4.y], a2 = g_td[i4.z], a3 = g_td[i4.w];
            st += (a0.x + a1.x) + (a2.x + a3.x);
            sd += (a0.y + a1.y) + (a2.y + a3.y);
        }
        for (; j < end; ++j) { float2 a = g_td[g_csr[j]]; st += a.x; sd += a.y; }
        u = d * st;
        g_rs[n] = d * sd;
    }
    float sm[16], sq[16], vv[16];
    #pragma unroll
    for (int c = 0; c < 16; ++c) {
        float v = valid ? geluf(fmaf(__ldg(&W1[c]), u, __ldg(&b1[c]))) : 0.f;
        vv[c] = v; sm[c] = v; sq[c] = v * v;
    }
    if (valid) {
        uint4 o0, o1;
        __half2 h;
        h = __floats2half2_rn(vv[0]*d,  vv[1]*d);  o0.x = *(unsigned*)&h;
        h = __floats2half2_rn(vv[2]*d,  vv[3]*d);  o0.y = *(unsigned*)&h;
        h = __floats2half2_rn(vv[4]*d,  vv[5]*d);  o0.z = *(unsigned*)&h;
        h = __floats2half2_rn(vv[6]*d,  vv[7]*d);  o0.w = *(unsigned*)&h;
        h = __floats2half2_rn(vv[8]*d,  vv[9]*d);  o1.x = *(unsigned*)&h;
        h = __floats2half2_rn(vv[10]*d, vv[11]*d); o1.y = *(unsigned*)&h;
        h = __floats2half2_rn(vv[12]*d, vv[13]*d); o1.z = *(unsigned*)&h;
        h = __floats2half2_rn(vv[14]*d, vv[15]*d); o1.w = *(unsigned*)&h;
        ((uint4*)&g_ya[n * 16])[0] = o0;
        ((uint4*)&g_ya[n * 16])[1] = o1;
    }
    #pragma unroll
    for (int off = 16; off > 0; off >>= 1) {
        #pragma unroll
        for (int c = 0; c < 16; ++c) {
            sm[c] += __shfl_xor_sync(0xffffffffu, sm[c], off);
            sq[c] += __shfl_xor_sync(0xffffffffu, sq[c], off);
        }
    }
    if ((threadIdx.x & 31) == 0) {
        #pragma unroll
        for (int c = 0; c < 16; ++c) {
            atomicAdd(&statsOut[c], sm[c]);
            atomicAdd(&statsOut[16 + c], sq[c]);
        }
    }
}

// ---------------- fused layer: gather(yin fp16, Cin) -> smem -> mm -> yout/pool
// phase A: node = tid/(2*WQ), quad = (rem)>>1, half k = rem&1 (2-way edge split)
// phase B: node = tid/CQ, out-quad c4 = tid%CQ
template<int Cin, int Cout, bool POOL>
__global__ void __launch_bounds__(256) k_layer(
        const __half* __restrict__ yin, __half* __restrict__ yout,
        const float* __restrict__ W, const float* __restrict__ bias,
        const float* __restrict__ gam, const float* __restrict__ bet,
        const float* __restrict__ statsIn, float* __restrict__ statsOut,
        const int* __restrict__ batch) {
    const int WQ  = Cin / 4;
    const int CQ  = Cout / 4;
    const int NPB = 256 / CQ;          // NPB*WQ*2 == 256 for all layers
    __shared__ float sc[64], shf[64], ut[512], sh[256];
    int tid = threadIdx.x;
    if (tid < Cin) {
        float mu  = statsIn[tid] * (1.0f / NN);
        float var = statsIn[Cin + tid] * (1.0f / NN) - mu * mu;
        float s = gam[tid] * rsqrtf(var + EPSF);
        sc[tid]  = s;
        shf[tid] = bet[tid] - mu * s;
    }
    if (!POOL) for (int i = tid; i < 2 * Cout; i += 256) sh[i] = 0.f;
    __syncthreads();

    int n0 = blockIdx.x * NPB;
    // ---- phase A: cooperative gather into ut ----
    {
        int node = tid / (2 * WQ);
        int rem  = tid - node * 2 * WQ;
        int q = rem >> 1, k = rem & 1;
        int n = n0 + node;
        const uint2* __restrict__ hw = (const uint2*)yin;
        float4 s = make_float4(0.f, 0.f, 0.f, 0.f);
        if (n < NN) {
            int rp = g_rowptr[n], re = g_rowptr[n + 1];
            int half = (re - rp) >> 1;
            int j    = k ? (rp + half) : rp;
            int jend = k ? re : (rp + half);
            if (k == 0) { uint2 u = hw[n * WQ + q]; acc_h(s, u); }   // self term
            while (j < jend && (j & 3)) acc_h(s, hw[g_csr[j++] * WQ + q]);
            for (; j + 8 <= jend; j += 8) {
                int4 a4 = *(const int4*)&g_csr[j];
                int4 b4 = *(const int4*)&g_csr[j + 4];
                uint2 u0 = hw[a4.x*WQ+q], u1 = hw[a4.y*WQ+q], u2 = hw[a4.z*WQ+q], u3 = hw[a4.w*WQ+q];
                uint2 u4 = hw[b4.x*WQ+q], u5 = hw[b4.y*WQ+q], u6 = hw[b4.z*WQ+q], u7 = hw[b4.w*WQ+q];
                acc_h(s, u0); acc_h(s, u1); acc_h(s, u2); acc_h(s, u3);
                acc_h(s, u4); acc_h(s, u5); acc_h(s, u6); acc_h(s, u7);
            }
            if (j + 4 <= jend) {
                int4 a4 = *(const int4*)&g_csr[j];
                uint2 u0 = hw[a4.x*WQ+q], u1 = hw[a4.y*WQ+q], u2 = hw[a4.z*WQ+q], u3 = hw[a4.w*WQ+q];
                acc_h(s, u0); acc_h(s, u1); acc_h(s, u2); acc_h(s, u3);
                j += 4;
            }
            for (; j < jend; ++j) acc_h(s, hw[g_csr[j] * WQ + q]);
        }
        // combine the two edge-halves (lanes 2m, 2m+1)
        s.x += __shfl_down_sync(0xffffffffu, s.x, 1);
        s.y += __shfl_down_sync(0xffffffffu, s.y, 1);
        s.z += __shfl_down_sync(0xffffffffu, s.z, 1);
        s.w += __shfl_down_sync(0xffffffffu, s.w, 1);
        if (k == 0) {
            int ci = q * 4;
            float* u = &ut[node * Cin + ci];
            if (n < NN) {
                float d = g_dis[n], rsv = g_rs[n];
                u[0] = fmaf(shf[ci + 0], rsv, sc[ci + 0] * (s.x * d));
                u[1] = fmaf(shf[ci + 1], rsv, sc[ci + 1] * (s.y * d));
                u[2] = fmaf(shf[ci + 2], rsv, sc[ci + 2] * (s.z * d));
                u[3] = fmaf(shf[ci + 3], rsv, sc[ci + 3] * (s.w * d));
            } else {
                u[0] = u[1] = u[2] = u[3] = 0.f;
            }
        }
    }
    __syncthreads();

    // ---- phase B: mm from ut ----
    int node = tid / CQ, c4 = tid - node * CQ;
    int n = n0 + node;
    bool valid = n < NN;
    const float4* __restrict__ Wv = (const float4*)W;
    float4 r = make_float4(0.f, 0.f, 0.f, 0.f);
    if (valid) {
        const float* a = &ut[node * Cin];
        float4 s = *(const float4*)&bias[c4 * 4];
        #pragma unroll
        for (int i = 0; i < Cin; ++i) {
            float av = a[i];
            float4 w = Wv[i * CQ + c4];
            s.x = fmaf(av, w.x, s.x); s.y = fmaf(av, w.y, s.y);
            s.z = fmaf(av, w.z, s.z); s.w = fmaf(av, w.w, s.w);
        }
        r.x = geluf(s.x); r.y = geluf(s.y); r.z = geluf(s.z); r.w = geluf(s.w);
        if (POOL) {
            int g = batch[n];
            red_add_v4(&g_pool[g * 128 + c4 * 4], r.x, r.y, r.z, r.w);
        } else {
            float d = g_dis[n];
            __half2 h0 = __floats2half2_rn(r.x * d, r.y * d);
            __half2 h1 = __floats2half2_rn(r.z * d, r.w * d);
            uint2 u; u.x = *(unsigned*)&h0; u.y = *(unsigned*)&h1;
            ((uint2*)yout)[n * CQ + c4] = u;
        }
    }
    if (!POOL) {
        float4 r2 = make_float4(r.x * r.x, r.y * r.y, r.z * r.z, r.w * r.w);
        #pragma unroll
        for (int off = CQ; off < 32; off <<= 1) {
            r.x  += __shfl_down_sync(0xffffffffu, r.x,  off);
            r.y  += __shfl_down_sync(0xffffffffu, r.y,  off);
            r.z  += __shfl_down_sync(0xffffffffu, r.z,  off);
            r.w  += __shfl_down_sync(0xffffffffu, r.w,  off);
            r2.x += __shfl_down_sync(0xffffffffu, r2.x, off);
            r2.y += __shfl_down_sync(0xffffffffu, r2.y, off);
            r2.z += __shfl_down_sync(0xffffffffu, r2.z, off);
            r2.w += __shfl_down_sync(0xffffffffu, r2.w, off);
        }
        if ((tid & 31) < CQ) {
            int c0 = (tid % CQ) * 4;
            atomicAdd(&sh[c0 + 0], r.x);  atomicAdd(&sh[Cout + c0 + 0], r2.x);
            atomicAdd(&sh[c0 + 1], r.y);  atomicAdd(&sh[Cout + c0 + 1], r2.y);
            atomicAdd(&sh[c0 + 2], r.z);  atomicAdd(&sh[Cout + c0 + 2], r2.z);
            atomicAdd(&sh[c0 + 3], r.w);  atomicAdd(&sh[Cout + c0 + 3], r2.w);
        }
        __syncthreads();
        for (int i = tid; i < 2 * Cout; i += 256) atomicAdd(&statsOut[i], sh[i]);
    }
}

// ---------------- fused MLP head -------------------------------------------------
__global__ void k_head(const int* __restrict__ batch, const float* __restrict__ yx,
                       const float* __restrict__ lw1, const float* __restrict__ lb1,
                       const float* __restrict__ lw2, const float* __restrict__ lb2,
                       const float* __restrict__ lw3, const float* __restrict__ lb3,
                       const float* __restrict__ lw4, const float* __restrict__ lb4,
                       float* __restrict__ out) {
    int g = blockIdx.x, tid = threadIdx.x;
    __shared__ float z[136], a1[128], a2[64], a3[32];
    __shared__ int bounds[2];
    if (tid < 2) {
        int key = g + tid;
        int lo = 0, hi = NN;
        while (lo < hi) {
            int mid = (lo + hi) >> 1;
            if (batch[mid] < key) lo = mid + 1; else hi = mid;
        }
        bounds[tid] = lo;
    }
    __syncthreads();
    float inv = 1.0f / fmaxf((float)(bounds[1] - bounds[0]), 1.0f);
    for (int j = tid; j < 135; j += 128)
        z[j] = (j < 128) ? g_pool[g * 128 + j] * inv : yx[g * 7 + (j - 128)];
    __syncthreads();
    {
        float s = lb1[tid];
        #pragma unroll 5
        for (int i = 0; i < 135; ++i) s = fmaf(z[i], lw1[i * 128 + tid], s);
        a1[tid] = geluf(s);
    }
    __syncthreads();
    if (tid < 64) {
        float s = lb2[tid];
        #pragma unroll 8
        for (int i = 0; i < 128; ++i) s = fmaf(a1[i], lw2[i * 64 + tid], s);
        a2[tid] = geluf(s);
    }
    __syncthreads();
    if (tid < 32) {
        float s = lb3[tid];
        #pragma unroll 8
        for (int i = 0; i < 64; ++i) s = fmaf(a2[i], lw3[i * 32 + tid], s);
        a3[tid] = geluf(s);
    }
    __syncthreads();
    if (tid < 2) {
        float s = lb4[tid];
        #pragma unroll
        for (int i = 0; i < 32; ++i) s = fmaf(a3[i], lw4[i * 2 + tid], s);
        out[g * 2 + tid] = 1.0f / (1.0f + expf(-s));
    }
}

// ---------------- host -------------------------------------------------------------
static inline int gs(int n) { return (n + 255) / 256; }

extern "C" void kernel_launch(void* const* d_in, const int* in_sizes, int n_in,
                              void* d_out, int out_size) {
    const float* x     = (const float*)d_in[0];
    const int*   ei    = (const int*)d_in[1];
    const int*   batch = (const int*)d_in[2];
    const float* yx    = (const float*)d_in[3];
    const float* W[4]  = {(const float*)d_in[4], (const float*)d_in[6],
                          (const float*)d_in[8], (const float*)d_in[10]};
    const float* B[4]  = {(const float*)d_in[5], (const float*)d_in[7],
                          (const float*)d_in[9], (const float*)d_in[11]};
    const float* Gm[3] = {(const float*)d_in[12], (const float*)d_in[14], (const float*)d_in[16]};
    const float* Be[3] = {(const float*)d_in[13], (const float*)d_in[15], (const float*)d_in[17]};
    const float* LW[4] = {(const float*)d_in[18], (const float*)d_in[20],
                          (const float*)d_in[22], (const float*)d_in[24]};
    const float* LB[4] = {(const float*)d_in[19], (const float*)d_in[21],
                          (const float*)d_in[23], (const float*)d_in[25]};

    void *p_cnt, *p_pool, *p_stats, *p_ya, *p_yb;
    cudaGetSymbolAddress(&p_cnt,   g_cnt);
    cudaGetSymbolAddress(&p_pool,  g_pool);
    cudaGetSymbolAddress(&p_stats, g_stats);
    cudaGetSymbolAddress(&p_ya,    g_ya);
    cudaGetSymbolAddress(&p_yb,    g_yb);
    float* stats = (float*)p_stats;
    __half* ya = (__half*)p_ya;
    __half* yb = (__half*)p_yb;

    cudaMemsetAsync(p_cnt,   0, NN * sizeof(int));
    cudaMemsetAsync(p_pool,  0, GG * 128 * sizeof(float));
    cudaMemsetAsync(p_stats, 0, 384 * sizeof(float));

    k_hist <<<gs(EE), 256>>>(ei);
    k_scanA<<<SCAN_B, 256>>>();
    k_scanB<<<1, 256>>>();
    k_scanC<<<SCAN_B, 256>>>(x);
    k_fill <<<gs(EE), 256>>>(ei);

    // layer 0: scalar gather -> ya fp16[16] + rs + stats0
    k_l0<<<gs(NN), 256>>>(W[0], B[0], stats + 0);

    // fused layers (ping-pong message buffers to avoid cross-block RAW race)
    k_layer<16, 32, false><<<(NN + 31) / 32, 256>>>(ya, yb, W[1], B[1], Gm[0], Be[0],
                                                    stats + 0, stats + 128, batch);
    k_layer<32, 64, false><<<(NN + 15) / 16, 256>>>(yb, ya, W[2], B[2], Gm[1], Be[1],
                                                    stats + 128, stats + 256, batch);
    k_layer<64, 128, true><<<(NN + 7) / 8, 256>>>(ya, yb, W[3], B[3], Gm[2], Be[2],
                                                  stats + 256, nullptr, batch);

    k_head<<<GG, 128>>>(batch, yx, LW[0], LB[0], LW[1], LB[1],
                        LW[2], LB[2], LW[3], LB[3], (float*)d_out);
}

// round 11
// speedup vs baseline: 1.3533x; 1.1074x over previous
#include <cuda_runtime.h>
#include <cuda_fp16.h>
#include <math.h>

#define NN 50000
#define EE 800000
#define GG 256
#define EPSF 1e-5f
#define SCAN_B 196   // ceil(50000/256)

// ---------------- scratch ----------------------------------------------------
__device__ __align__(256) __half g_ya[NN * 64];     // message ping buffer
__device__ __align__(256) __half g_yb[NN * 64];     // message pong buffer
__device__ __align__(256) float  g_dis[NN];
__device__ __align__(256) float  g_rs[NN];          // dis*(dis + sum dis[src])
__device__ __align__(256) float2 g_td[NN];          // (x*dis, dis)
__device__ __align__(256) int    g_cnt[NN];
__device__ __align__(256) int    g_rowptr[NN + 1];
__device__ __align__(256) int    g_cur[NN];
__device__ __align__(256) int    g_csr[EE];
__device__ __align__(256) int    g_bsum[SCAN_B];
__device__ __align__(256) float  g_stats[384];
__device__ __align__(256) float  g_pool[GG * 128];

__device__ __forceinline__ float geluf(float x) {
    return 0.5f * x * (1.0f + erff(x * 0.70710678118654752f));
}
__device__ __forceinline__ void red_add_v4(float* addr, float a, float b, float c, float d) {
    asm volatile("red.global.add.v4.f32 [%0], {%1,%2,%3,%4};"
                 :: "l"(addr), "f"(a), "f"(b), "f"(c), "f"(d) : "memory");
}
__device__ __forceinline__ void acc_h(float4& s, uint2 u) {
    float2 f0 = __half22float2(*(__half2*)&u.x);
    float2 f1 = __half22float2(*(__half2*)&u.y);
    s.x += f0.x; s.y += f0.y; s.z += f1.x; s.w += f1.y;
}

// ---------------- CSR build ---------------------------------------------------
__global__ void k_hist(const int* __restrict__ ei) {
    int e = blockIdx.x * blockDim.x + threadIdx.x;
    if (e < EE) atomicAdd(&g_cnt[ei[EE + e]], 1);
}
__global__ void k_scanA() {
    __shared__ int sh[256];
    int i = blockIdx.x * 256 + threadIdx.x;
    sh[threadIdx.x] = (i < NN) ? g_cnt[i] : 0;
    __syncthreads();
    for (int o = 128; o > 0; o >>= 1) {
        if (threadIdx.x < o) sh[threadIdx.x] += sh[threadIdx.x + o];
        __syncthreads();
    }
    if (threadIdx.x == 0) g_bsum[blockIdx.x] = sh[0];
}
__global__ void k_scanB() {
    __shared__ int sh[256];
    int t = threadIdx.x;
    int v = (t < SCAN_B) ? g_bsum[t] : 0;
    sh[t] = v;
    __syncthreads();
    for (int o = 1; o < 256; o <<= 1) {
        int u = (t >= o) ? sh[t - o] : 0;
        __syncthreads();
        sh[t] += u;
        __syncthreads();
    }
    if (t < SCAN_B) g_bsum[t] = sh[t] - v;
    if (t == 0) g_rowptr[NN] = EE;
}
__global__ void k_scanC(const float* __restrict__ x) {
    __shared__ int sh[256];
    int i = blockIdx.x * 256 + threadIdx.x;
    int t = threadIdx.x;
    int c = (i < NN) ? g_cnt[i] : 0;
    sh[t] = c;
    __syncthreads();
    for (int o = 1; o < 256; o <<= 1) {
        int u = (t >= o) ? sh[t - o] : 0;
        __syncthreads();
        sh[t] += u;
        __syncthreads();
    }
    if (i < NN) {
        int rp = g_bsum[blockIdx.x] + sh[t] - c;
        g_rowptr[i] = rp;
        g_cur[i]    = rp;
        float d = rsqrtf((float)c + 1.0f);
        g_dis[i]  = d;
        g_td[i]   = make_float2(x[i] * d, d);
    }
}
__global__ void k_fill(const int* __restrict__ ei) {
    int e = blockIdx.x * blockDim.x + threadIdx.x;
    if (e < EE) {
        int pos = atomicAdd(&g_cur[ei[EE + e]], 1);
        g_csr[pos] = ei[e];
    }
}

// ---------------- layer 0: scalar gather (x*dis AND dis) + expand + gelu + stats
__global__ void k_l0(const float* __restrict__ W1, const float* __restrict__ b1,
                     float* __restrict__ statsOut) {
    int n = blockIdx.x * 256 + threadIdx.x;
    bool valid = n < NN;
    float u = 0.f, d = 0.f;
    if (valid) {
        float2 self = g_td[n];
        d = self.y;
        float st = self.x, sd = self.y;
        int j = g_rowptr[n], end = g_rowptr[n + 1];
        while (j < end && (j & 3)) { float2 a = g_td[g_csr[j++]]; st += a.x; sd += a.y; }
        for (; j + 4 <= end; j += 4) {
            int4 i4 = *(const int4*)&g_csr[j];
            float2 a0 = g_td[i4.x], a1 = g_td[i4.y], a2 = g_td[i4.z], a3 = g_td[i4.w];
            st += (a0.x + a1.x) + (a2.x + a3.x);
            sd += (a0.y + a1.y) + (a2.y + a3.y);
        }
        for (; j < end; ++j) { float2 a = g_td[g_csr[j]]; st += a.x; sd += a.y; }
        u = d * st;
        g_rs[n] = d * sd;
    }
    float sm[16], sq[16], vv[16];
    #pragma unroll
    for (int c = 0; c < 16; ++c) {
        float v = valid ? geluf(fmaf(__ldg(&W1[c]), u, __ldg(&b1[c]))) : 0.f;
        vv[c] = v; sm[c] = v; sq[c] = v * v;
    }
    if (valid) {
        uint4 o0, o1;
        __half2 h;
        h = __floats2half2_rn(vv[0]*d,  vv[1]*d);  o0.x = *(unsigned*)&h;
        h = __floats2half2_rn(vv[2]*d,  vv[3]*d);  o0.y = *(unsigned*)&h;
        h = __floats2half2_rn(vv[4]*d,  vv[5]*d);  o0.z = *(unsigned*)&h;
        h = __floats2half2_rn(vv[6]*d,  vv[7]*d);  o0.w = *(unsigned*)&h;
        h = __floats2half2_rn(vv[8]*d,  vv[9]*d);  o1.x = *(unsigned*)&h;
        h = __floats2half2_rn(vv[10]*d, vv[11]*d); o1.y = *(unsigned*)&h;
        h = __floats2half2_rn(vv[12]*d, vv[13]*d); o1.z = *(unsigned*)&h;
        h = __floats2half2_rn(vv[14]*d, vv[15]*d); o1.w = *(unsigned*)&h;
        ((uint4*)&g_ya[n * 16])[0] = o0;
        ((uint4*)&g_ya[n * 16])[1] = o1;
    }
    #pragma unroll
    for (int off = 16; off > 0; off >>= 1) {
        #pragma unroll
        for (int c = 0; c < 16; ++c) {
            sm[c] += __shfl_xor_sync(0xffffffffu, sm[c], off);
            sq[c] += __shfl_xor_sync(0xffffffffu, sq[c], off);
        }
    }
    if ((threadIdx.x & 31) == 0) {
        #pragma unroll
        for (int c = 0; c < 16; ++c) {
            atomicAdd(&statsOut[c], sm[c]);
            atomicAdd(&statsOut[16 + c], sq[c]);
        }
    }
}

// ---------------- fused layer: 32-node tile, gather -> smem -> W-hoisted mm ----
template<int Cin, int Cout, bool POOL>
__global__ void __launch_bounds__(256) k_layer(
        const __half* __restrict__ yin, __half* __restrict__ yout,
        const float* __restrict__ W, const float* __restrict__ bias,
        const float* __restrict__ gam, const float* __restrict__ bet,
        const float* __restrict__ statsIn, float* __restrict__ statsOut,
        const int* __restrict__ batch) {
    const int WQ    = Cin / 4;
    const int CQ    = Cout / 4;
    const int TILE  = 32;                // nodes per block
    const int NPB_A = 256 / (2 * WQ);    // nodes per gather pass
    const int PASSES = TILE / NPB_A;
    const int SLOTS = 256 / CQ;          // concurrent nodes in mm
    const int NITER = TILE / SLOTS;      // nodes per thread in mm
    __shared__ float sc[64], shf[64], sh[256];
    __shared__ float ut[TILE * Cin];     // <= 8 KB
    int tid = threadIdx.x;
    if (tid < Cin) {
        float mu  = statsIn[tid] * (1.0f / NN);
        float var = statsIn[Cin + tid] * (1.0f / NN) - mu * mu;
        float s = gam[tid] * rsqrtf(var + EPSF);
        sc[tid]  = s;
        shf[tid] = bet[tid] - mu * s;
    }
    if (!POOL) for (int i = tid; i < 2 * Cout; i += 256) sh[i] = 0.f;
    __syncthreads();

    int n0 = blockIdx.x * TILE;
    // ---- phase A: cooperative gather into ut (2-way edge split per quad) ----
    {
        int nodeA = tid / (2 * WQ);
        int rem   = tid - nodeA * 2 * WQ;
        int q = rem >> 1, k = rem & 1;
        const uint2* __restrict__ hw = (const uint2*)yin;
        #pragma unroll
        for (int p = 0; p < PASSES; ++p) {
            int nl = p * NPB_A + nodeA;
            int n  = n0 + nl;
            float4 s = make_float4(0.f, 0.f, 0.f, 0.f);
            if (n < NN) {
                int rp = g_rowptr[n], re = g_rowptr[n + 1];
                int half = (re - rp) >> 1;
                int j    = k ? (rp + half) : rp;
                int jend = k ? re : (rp + half);
                if (k == 0) { uint2 u = hw[n * WQ + q]; acc_h(s, u); }   // self
                while (j < jend && (j & 3)) acc_h(s, hw[g_csr[j++] * WQ + q]);
                for (; j + 8 <= jend; j += 8) {
                    int4 a4 = *(const int4*)&g_csr[j];
                    int4 b4 = *(const int4*)&g_csr[j + 4];
                    uint2 u0 = hw[a4.x*WQ+q], u1 = hw[a4.y*WQ+q], u2 = hw[a4.z*WQ+q], u3 = hw[a4.w*WQ+q];
                    uint2 u4 = hw[b4.x*WQ+q], u5 = hw[b4.y*WQ+q], u6 = hw[b4.z*WQ+q], u7 = hw[b4.w*WQ+q];
                    acc_h(s, u0); acc_h(s, u1); acc_h(s, u2); acc_h(s, u3);
                    acc_h(s, u4); acc_h(s, u5); acc_h(s, u6); acc_h(s, u7);
                }
                if (j + 4 <= jend) {
                    int4 a4 = *(const int4*)&g_csr[j];
                    uint2 u0 = hw[a4.x*WQ+q], u1 = hw[a4.y*WQ+q], u2 = hw[a4.z*WQ+q], u3 = hw[a4.w*WQ+q];
                    acc_h(s, u0); acc_h(s, u1); acc_h(s, u2); acc_h(s, u3);
                    j += 4;
                }
                for (; j < jend; ++j) acc_h(s, hw[g_csr[j] * WQ + q]);
            }
            s.x += __shfl_down_sync(0xffffffffu, s.x, 1);
            s.y += __shfl_down_sync(0xffffffffu, s.y, 1);
            s.z += __shfl_down_sync(0xffffffffu, s.z, 1);
            s.w += __shfl_down_sync(0xffffffffu, s.w, 1);
            if (k == 0) {
                int ci = q * 4;
                float* u = &ut[nl * Cin + ci];
                if (n < NN) {
                    float d = g_dis[n], rsv = g_rs[n];
                    u[0] = fmaf(shf[ci + 0], rsv, sc[ci + 0] * (s.x * d));
                    u[1] = fmaf(shf[ci + 1], rsv, sc[ci + 1] * (s.y * d));
                    u[2] = fmaf(shf[ci + 2], rsv, sc[ci + 2] * (s.z * d));
                    u[3] = fmaf(shf[ci + 3], rsv, sc[ci + 3] * (s.w * d));
                } else {
                    u[0] = u[1] = u[2] = u[3] = 0.f;
                }
            }
        }
    }
    __syncthreads();

    // ---- phase B: W-hoisted mm over NITER nodes per thread ----
    int c4 = tid % CQ, slot = tid / CQ;
    const float4* __restrict__ Wv = (const float4*)W;
    float4 bb = *(const float4*)&bias[c4 * 4];
    float4 acc[NITER];
    #pragma unroll
    for (int k = 0; k < NITER; ++k) acc[k] = bb;
    #pragma unroll 4
    for (int i = 0; i < Cin; ++i) {
        float4 w = Wv[i * CQ + c4];
        #pragma unroll
        for (int k = 0; k < NITER; ++k) {
            float av = ut[(slot + k * SLOTS) * Cin + i];
            acc[k].x = fmaf(av, w.x, acc[k].x);
            acc[k].y = fmaf(av, w.y, acc[k].y);
            acc[k].z = fmaf(av, w.z, acc[k].z);
            acc[k].w = fmaf(av, w.w, acc[k].w);
        }
    }
    float4 rsum = make_float4(0.f, 0.f, 0.f, 0.f);
    float4 r2sum = make_float4(0.f, 0.f, 0.f, 0.f);
    #pragma unroll
    for (int k = 0; k < NITER; ++k) {
        int n = n0 + slot + k * SLOTS;
        if (n >= NN) continue;
        float4 r;
        r.x = geluf(acc[k].x); r.y = geluf(acc[k].y);
        r.z = geluf(acc[k].z); r.w = geluf(acc[k].w);
        if (POOL) {
            int g = batch[n];
            red_add_v4(&g_pool[g * 128 + c4 * 4], r.x, r.y, r.z, r.w);
        } else {
            float d = g_dis[n];
            __half2 h0 = __floats2half2_rn(r.x * d, r.y * d);
            __half2 h1 = __floats2half2_rn(r.z * d, r.w * d);
            uint2 u; u.x = *(unsigned*)&h0; u.y = *(unsigned*)&h1;
            ((uint2*)yout)[n * CQ + c4] = u;
            rsum.x += r.x; rsum.y += r.y; rsum.z += r.z; rsum.w += r.w;
            r2sum.x += r.x * r.x; r2sum.y += r.y * r.y;
            r2sum.z += r.z * r.z; r2sum.w += r.w * r.w;
        }
    }
    if (!POOL) {
        #pragma unroll
        for (int off = CQ; off < 32; off <<= 1) {
            rsum.x  += __shfl_down_sync(0xffffffffu, rsum.x,  off);
            rsum.y  += __shfl_down_sync(0xffffffffu, rsum.y,  off);
            rsum.z  += __shfl_down_sync(0xffffffffu, rsum.z,  off);
            rsum.w  += __shfl_down_sync(0xffffffffu, rsum.w,  off);
            r2sum.x += __shfl_down_sync(0xffffffffu, r2sum.x, off);
            r2sum.y += __shfl_down_sync(0xffffffffu, r2sum.y, off);
            r2sum.z += __shfl_down_sync(0xffffffffu, r2sum.z, off);
            r2sum.w += __shfl_down_sync(0xffffffffu, r2sum.w, off);
        }
        if ((tid & 31) < CQ) {
            int c0 = (tid % CQ) * 4;
            atomicAdd(&sh[c0 + 0], rsum.x);  atomicAdd(&sh[Cout + c0 + 0], r2sum.x);
            atomicAdd(&sh[c0 + 1], rsum.y);  atomicAdd(&sh[Cout + c0 + 1], r2sum.y);
            atomicAdd(&sh[c0 + 2], rsum.z);  atomicAdd(&sh[Cout + c0 + 2], r2sum.z);
            atomicAdd(&sh[c0 + 3], rsum.w);  atomicAdd(&sh[Cout + c0 + 3], r2sum.w);
        }
        __syncthreads();
        for (int i = tid; i < 2 * Cout; i += 256) atomicAdd(&statsOut[i], sh[i]);
    }
}

// ---------------- fused MLP head -------------------------------------------------
__global__ void k_head(const int* __restrict__ batch, const float* __restrict__ yx,
                       const float* __restrict__ lw1, const float* __restrict__ lb1,
                       const float* __restrict__ lw2, const float* __restrict__ lb2,
                       const float* __restrict__ lw3, const float* __restrict__ lb3,
                       const float* __restrict__ lw4, const float* __restrict__ lb4,
                       float* __restrict__ out) {
    int g = blockIdx.x, tid = threadIdx.x;
    __shared__ float z[136], a1[128], a2[64], a3[32];
    __shared__ int bounds[2];
    if (tid < 2) {
        int key = g + tid;
        int lo = 0, hi = NN;
        while (lo < hi) {
            int mid = (lo + hi) >> 1;
            if (batch[mid] < key) lo = mid + 1; else hi = mid;
        }
        bounds[tid] = lo;
    }
    __syncthreads();
    float inv = 1.0f / fmaxf((float)(bounds[1] - bounds[0]), 1.0f);
    for (int j = tid; j < 135; j += 128)
        z[j] = (j < 128) ? g_pool[g * 128 + j] * inv : yx[g * 7 + (j - 128)];
    __syncthreads();
    {
        float s = lb1[tid];
        #pragma unroll 5
        for (int i = 0; i < 135; ++i) s = fmaf(z[i], lw1[i * 128 + tid], s);
        a1[tid] = geluf(s);
    }
    __syncthreads();
    if (tid < 64) {
        float s = lb2[tid];
        #pragma unroll 8
        for (int i = 0; i < 128; ++i) s = fmaf(a1[i], lw2[i * 64 + tid], s);
        a2[tid] = geluf(s);
    }
    __syncthreads();
    if (tid < 32) {
        float s = lb3[tid];
        #pragma unroll 8
        for (int i = 0; i < 64; ++i) s = fmaf(a2[i], lw3[i * 32 + tid], s);
        a3[tid] = geluf(s);
    }
    __syncthreads();
    if (tid < 2) {
        float s = lb4[tid];
        #pragma unroll
        for (int i = 0; i < 32; ++i) s = fmaf(a3[i], lw4[i * 2 + tid], s);
        out[g * 2 + tid] = 1.0f / (1.0f + expf(-s));
    }
}

// ---------------- host -------------------------------------------------------------
static inline int gs(int n) { return (n + 255) / 256; }

extern "C" void kernel_launch(void* const* d_in, const int* in_sizes, int n_in,
                              void* d_out, int out_size) {
    const float* x     = (const float*)d_in[0];
    const int*   ei    = (const int*)d_in[1];
    const int*   batch = (const int*)d_in[2];
    const float* yx    = (const float*)d_in[3];
    const float* W[4]  = {(const float*)d_in[4], (const float*)d_in[6],
                          (const float*)d_in[8], (const float*)d_in[10]};
    const float* B[4]  = {(const float*)d_in[5], (const float*)d_in[7],
                          (const float*)d_in[9], (const float*)d_in[11]};
    const float* Gm[3] = {(const float*)d_in[12], (const float*)d_in[14], (const float*)d_in[16]};
    const float* Be[3] = {(const float*)d_in[13], (const float*)d_in[15], (const float*)d_in[17]};
    const float* LW[4] = {(const float*)d_in[18], (const float*)d_in[20],
                          (const float*)d_in[22], (const float*)d_in[24]};
    const float* LB[4] = {(const float*)d_in[19], (const float*)d_in[21],
                          (const float*)d_in[23], (const float*)d_in[25]};

    void *p_cnt, *p_pool, *p_stats, *p_ya, *p_yb;
    cudaGetSymbolAddress(&p_cnt,   g_cnt);
    cudaGetSymbolAddress(&p_pool,  g_pool);
    cudaGetSymbolAddress(&p_stats, g_stats);
    cudaGetSymbolAddress(&p_ya,    g_ya);
    cudaGetSymbolAddress(&p_yb,    g_yb);
    float* stats = (float*)p_stats;
    __half* ya = (__half*)p_ya;
    __half* yb = (__half*)p_yb;

    cudaMemsetAsync(p_cnt,   0, NN * sizeof(int));
    cudaMemsetAsync(p_pool,  0, GG * 128 * sizeof(float));
    cudaMemsetAsync(p_stats, 0, 384 * sizeof(float));

    k_hist <<<gs(EE), 256>>>(ei);
    k_scanA<<<SCAN_B, 256>>>();
    k_scanB<<<1, 256>>>();
    k_scanC<<<SCAN_B, 256>>>(x);
    k_fill <<<gs(EE), 256>>>(ei);

    // layer 0: scalar gather -> ya fp16[16] + rs + stats0
    k_l0<<<gs(NN), 256>>>(W[0], B[0], stats + 0);

    // fused layers, 32-node tiles (ping-pong message buffers)
    const int TB = (NN + 31) / 32;
    k_layer<16, 32, false><<<TB, 256>>>(ya, yb, W[1], B[1], Gm[0], Be[0],
                                        stats + 0, stats + 128, batch);
    k_layer<32, 64, false><<<TB, 256>>>(yb, ya, W[2], B[2], Gm[1], Be[1],
                                        stats + 128, stats + 256, batch);
    k_layer<64, 128, true><<<TB, 256>>>(ya, yb, W[3], B[3], Gm[2], Be[2],
                                        stats + 256, nullptr, batch);

    k_head<<<GG, 128>>>(batch, yx, LW[0], LB[0], LW[1], LB[1],
                        LW[2], LB[2], LW[3], LB[3], (float*)d_out);
}